// round 15
// baseline (speedup 1.0000x reference)
#include <cuda_runtime.h>
#include <cstdint>

// Problem constants (fixed shapes)
#define Nb    16
#define C     30
#define H     128
#define W     128
#define HW    (H*W)            // 16384
#define TOT   (HW*C)           // 491520 per batch
#define K     1000
#define NBINS 1024
#define BSHIFT 14
#define LOBITS 0x3E99999Au     // __float_as_uint(0.3f)
#define CAP   2048
#define TH    0.3f
#define XTH   (-0.8473f)       // logit(0.3) = -0.84729786; slightly below, safe pre-filter

// Static scratch (no allocations allowed; zero-initialized at module load)
__device__ unsigned int       g_hist[Nb*NBINS];          // zeroed by sortcut after use
__device__ unsigned int       g_na[Nb];                  // zeroed by sortcut after use
__device__ unsigned int       g_sel[Nb];
__device__ unsigned long long g_all[(size_t)Nb*TOT];     // worst-case candidate store
__device__ unsigned long long g_top[Nb*K];

__device__ __forceinline__ float sigm(float x) {
    return 1.0f / (1.0f + expf(-x));   // must stay expf: score rounding defines the ordering
}

// ---------------------------------------------------------------- kernel 1:
// single streaming pass: histogram score bits + warp-aggregated compaction of
// all >TH candidates directly to global (no smem staging, no chunk syncs)
__global__ void __launch_bounds__(256)
histcompact_kernel(const float* __restrict__ sCls) {
    __shared__ unsigned int sh[NBINS];           // 4 KB
    const int b    = blockIdx.y;
    const int tid  = threadIdx.x;
    const int lane = tid & 31;

    for (int i = tid; i < NBINS; i += 256) sh[i] = 0u;
    __syncthreads();

    const float4* p  = (const float4*)(sCls + (size_t)b * TOT);
    const int nv4    = TOT / 4;               // 122880
    const int per    = nv4 / gridDim.x;       // gridDim.x = 128 -> 960
    const int start  = blockIdx.x * per;
    const int endf4  = start + per;

    unsigned long long* dst = &g_all[(size_t)b * TOT];

    for (int i = start + tid; i < endf4; i += 256) {
        float4 v = p[i];
        float vv[4] = {v.x, v.y, v.z, v.w};
        #pragma unroll
        for (int j = 0; j < 4; j++) {
            bool pred = false;
            unsigned int sb = 0u;
            if (vv[j] > XTH) {
                float s = sigm(vv[j]);
                if (s > TH) { pred = true; sb = __float_as_uint(s); }
            }
            unsigned int mask = __ballot_sync(0xFFFFFFFFu, pred);
            if (pred) {
                unsigned int bin = (sb - LOBITS) >> BSHIFT;
                if (bin > NBINS-1u) bin = NBINS-1u;
                atomicAdd(&sh[bin], 1u);
                int leader          = __ffs(mask) - 1;
                unsigned int wcnt   = __popc(mask);
                unsigned int prefix = __popc(mask & ((1u << lane) - 1u));
                unsigned int base;
                if (lane == leader) base = atomicAdd(&g_na[b], wcnt);
                base = __shfl_sync(mask, base, leader);
                int e   = i*4 + j;                 // linear within [C, HW]
                int ch  = e >> 14;                 // channel (HW = 2^14)
                int loc = e & (HW-1);
                unsigned int flat = (unsigned)(loc*C + ch);
                dst[base + prefix] = ((unsigned long long)sb << 32) |
                                     (unsigned long long)(~flat);
            }
        }
    }
    __syncthreads();
    for (int i = tid; i < NBINS; i += 256) {
        unsigned int c = sh[i];
        if (c) atomicAdd(&g_hist[b*NBINS + i], c);
    }
}

// ---------------------------------------------------------------- kernel 2:
// fused: cut-bin selection (block scan over hist) + filter + adaptive bitonic
__global__ void __launch_bounds__(1024)
sortcut_kernel() {
    const int b    = blockIdx.x;
    const int tid  = threadIdx.x;
    const int lane = tid & 31;
    const int wid  = tid >> 5;
    __shared__ unsigned long long sk[CAP];       // 16 KB
    __shared__ unsigned int wsum[32];
    __shared__ int s_cut;
    __shared__ unsigned int scnt;

    // ---- phase A: find cut bin (descending cumulative over 1024 bins)
    const int base = b * NBINS;
    unsigned int cnt = g_hist[base + (NBINS-1 - tid)];   // t=0 -> highest bin
    g_hist[base + (NBINS-1 - tid)] = 0u;                 // restore invariant
    unsigned int x = cnt;
    #pragma unroll
    for (int o = 1; o < 32; o <<= 1) {
        unsigned int y = __shfl_up_sync(0xFFFFFFFFu, x, o);
        if (lane >= o) x += y;
    }
    if (lane == 31) wsum[wid] = x;
    if (tid == 0) scnt = 0u;
    __syncthreads();
    if (wid == 0) {
        unsigned int v  = wsum[lane];
        unsigned int xx = v;
        #pragma unroll
        for (int o = 1; o < 32; o <<= 1) {
            unsigned int y = __shfl_up_sync(0xFFFFFFFFu, xx, o);
            if (lane >= o) xx += y;
        }
        wsum[lane] = xx - v;                              // exclusive warp offsets
        if (lane == 31 && xx < (unsigned)K) s_cut = 0;    // total < K: take all
    }
    __syncthreads();
    unsigned int excl = (x - cnt) + wsum[wid];
    if (excl < (unsigned)K && excl + cnt >= (unsigned)K)
        s_cut = NBINS-1 - tid;                            // exactly one crossing
    __syncthreads();

    // ---- phase B: filter candidates (bin >= cut) from L2-resident list
    const int cut   = s_cut;
    unsigned int na = g_na[b];
    for (int i = tid; i < CAP; i += 1024) sk[i] = 0ULL;
    __syncthreads();

    const unsigned long long* src = &g_all[(size_t)b*TOT];
    for (unsigned int i = tid; i < na; i += 1024) {
        unsigned long long key = __ldg(&src[i]);
        unsigned int sb  = (unsigned int)(key >> 32);
        unsigned int bin = (sb - LOBITS) >> BSHIFT;
        if (bin > NBINS-1u) bin = NBINS-1u;
        if ((int)bin >= cut) {
            unsigned int pos = atomicAdd(&scnt, 1u);
            if (pos < CAP) sk[pos] = key;
        }
    }
    __syncthreads();

    // ---- phase C: bitonic sort, descending, adaptive size (1024 common case)
    const unsigned int sel = scnt;
    const int M = (sel <= 1024u) ? 1024 : CAP;
    for (int size = 2; size <= M; size <<= 1) {
        for (int stride = size >> 1; stride > 0; stride >>= 1) {
            __syncthreads();
            for (int i = tid; i < M; i += 1024) {
                int j = i ^ stride;
                if (j > i) {
                    bool descSeg = ((i & size) == 0);
                    unsigned long long a = sk[i], bb = sk[j];
                    if (descSeg ? (a < bb) : (a > bb)) { sk[i] = bb; sk[j] = a; }
                }
            }
        }
    }
    __syncthreads();

    for (int k = tid; k < K; k += 1024) g_top[b*K + k] = sk[k];
    if (tid == 0) {
        g_sel[b] = (sel > (unsigned)K) ? (unsigned)K : sel;
        g_na[b]  = 0u;                            // restore invariant
    }
}

// ---------------------------------------------------------------- kernel 3:
// decode + scattered sReg gather + anchor decode + write (parallel over all rows)
__global__ void __launch_bounds__(128)
emit_kernel(const float* __restrict__ sReg,
            const float* __restrict__ anchors,
            float* __restrict__ out) {
    const int bx = blockIdx.x;                   // 128 blocks: 16 batches x 8
    const int b  = bx >> 3;
    const int k  = (bx & 7) * 128 + threadIdx.x; // 0..1023
    if (k >= K) return;

    float* det = out + ((size_t)b*K + k) * 16;
    float* lab = out + (size_t)Nb*K*16 + (size_t)b*K + k;
    float* sco = out + (size_t)Nb*K*17 + (size_t)b*K + k;

    if (k < (int)g_sel[b]) {
        unsigned long long key = g_top[b*K + k];
        unsigned int sb  = (unsigned int)(key >> 32);
        unsigned int idx = ~(unsigned int)(key & 0xFFFFFFFFu);
        float s  = __uint_as_float(sb);
        int loc  = idx / C;
        int cls  = idx - loc * C;
        float4 anc = ((const float4*)anchors)[loc];
        float wa = anc.z - anc.x, ha = anc.w - anc.y;
        float cx = 0.5f*(anc.x + anc.z), cy = 0.5f*(anc.y + anc.w);
        const float* regp = sReg + ((size_t)b*(C*16) + (size_t)cls*16) * HW + loc;
        float r[16];
        #pragma unroll
        for (int j = 0; j < 16; j++) r[j] = __ldg(&regp[(size_t)j * HW]);
        float o[16];
        #pragma unroll
        for (int j = 0; j < 8; j++)  o[j]     = r[j]     * wa + cx;
        #pragma unroll
        for (int j = 0; j < 8; j++)  o[8 + j] = r[8 + j] * ha + cy;
        #pragma unroll
        for (int j = 0; j < 4; j++)
            ((float4*)det)[j] = make_float4(o[4*j], o[4*j+1], o[4*j+2], o[4*j+3]);
        *lab = (float)(cls + 1);
        *sco = sqrtf(s);
    } else {
        #pragma unroll
        for (int j = 0; j < 4; j++)
            ((float4*)det)[j] = make_float4(0.f, 0.f, 0.f, 0.f);
        *lab = 0.0f;
        *sco = 0.0f;
    }
}

// ---------------------------------------------------------------- launcher
extern "C" void kernel_launch(void* const* d_in, const int* in_sizes, int n_in,
                              void* d_out, int out_size) {
    const float* sCls    = (const float*)d_in[0];
    const float* sReg    = (const float*)d_in[1];
    const float* anchors = (const float*)d_in[2];
    float* out = (float*)d_out;

    {
        dim3 grid(128, Nb);                  // 2048 blocks
        histcompact_kernel<<<grid, 256>>>(sCls);
    }
    sortcut_kernel<<<Nb, 1024>>>();
    emit_kernel<<<Nb*8, 128>>>(sReg, anchors, out);
}